// round 5
// baseline (speedup 1.0000x reference)
#include <cuda_runtime.h>
#include <cuda_bf16.h>

#define PLANES 48  // B*C = 16*3

// ---------------- static device scratch (no allocations allowed) ----------------
__device__ float g_d1[2][PLANES * 256 * 256];  // level-0 downs == level-1 currents
__device__ float g_d2[2][PLANES * 128 * 128];  // level-1 downs == level-2 currents
__device__ float g_d3[2][PLANES * 64 * 64];    // level-2 downs
__device__ double g_acc[3];                    // per-level |.| sums

// reflect index (numpy 'reflect', pad<=2): -1->1, -2->2, n->n-2, n+1->n-3
__device__ __forceinline__ int refl(int p, int n) {
    p = (p < 0) ? -p : p;
    return (p >= n) ? (2 * n - 2 - p) : p;
}

__global__ void zero_acc_kernel() {
    if (threadIdx.x < 3) g_acc[threadIdx.x] = 0.0;
}

// -------------------------------------------------------------------------------
// down_kernel<LVL>: 5x5 reflect gauss + ::2 decimation, separable, deinterleaved smem.
// block (32,8) -> 32x8 down pixels.  grid: (N2/32, N2/8, 96); z<48 -> image A.
// -------------------------------------------------------------------------------
template <int LVL>
__global__ __launch_bounds__(256) void down_kernel(const float* __restrict__ extA,
                                                   const float* __restrict__ extB) {
    constexpr int N  = (LVL == 0) ? 512 : (LVL == 1) ? 256 : 128;
    constexpr int N2 = N >> 1;

    const int z = blockIdx.z;
    const int p = (z < PLANES) ? z : z - PLANES;
    const float* cur;
    float* dn;
    if constexpr (LVL == 0) {
        cur = ((z < PLANES) ? extA : extB) + (size_t)p * N * N;
        dn  = ((z < PLANES) ? g_d1[0] : g_d1[1]) + (size_t)p * N2 * N2;
    } else if constexpr (LVL == 1) {
        cur = ((z < PLANES) ? g_d1[0] : g_d1[1]) + (size_t)p * N * N;
        dn  = ((z < PLANES) ? g_d2[0] : g_d2[1]) + (size_t)p * N2 * N2;
    } else {
        cur = ((z < PLANES) ? g_d2[0] : g_d2[1]) + (size_t)p * N * N;
        dn  = ((z < PLANES) ? g_d3[0] : g_d3[1]) + (size_t)p * N2 * N2;
    }

    __shared__ float s_e[19][34];   // even source cols
    __shared__ float s_o[19][34];   // odd source cols
    __shared__ float t_e[8][34];    // vertically filtered, even cols
    __shared__ float t_o[8][34];    // vertically filtered, odd cols
    __shared__ int colmap[67];
    __shared__ int rowoff[19];

    const int i0 = blockIdx.y * 8, j0 = blockIdx.x * 32;
    const int r0 = 2 * i0 - 2, c0 = 2 * j0 - 2;
    const int tid = threadIdx.y * 32 + threadIdx.x;

    if (tid < 67) colmap[tid] = refl(c0 + tid, N);
    if (tid >= 128 && tid < 128 + 19) rowoff[tid - 128] = refl(r0 + tid - 128, N) * N;
    __syncthreads();

    for (int idx = tid; idx < 19 * 67; idx += 256) {
        int r = idx / 67, c = idx - r * 67;
        float v = __ldg(&cur[rowoff[r] + colmap[c]]);
        if (c & 1) s_o[r][c >> 1] = v;
        else       s_e[r][c >> 1] = v;
    }
    __syncthreads();

    // vertical 5-tap [1,4,6,4,1] at down rows
    for (int idx = tid; idx < 8 * 34; idx += 256) {
        int i = idx / 34, c = idx - i * 34;
        t_e[i][c] = s_e[2 * i][c] + 4.f * s_e[2 * i + 1][c] + 6.f * s_e[2 * i + 2][c]
                  + 4.f * s_e[2 * i + 3][c] + s_e[2 * i + 4][c];
    }
    for (int idx = tid; idx < 8 * 33; idx += 256) {
        int i = idx / 33, c = idx - i * 33;
        t_o[i][c] = s_o[2 * i][c] + 4.f * s_o[2 * i + 1][c] + 6.f * s_o[2 * i + 2][c]
                  + 4.f * s_o[2 * i + 3][c] + s_o[2 * i + 4][c];
    }
    __syncthreads();

    // horizontal: even taps {1,6,1} at e[lj..lj+2], odd taps {4,4} at o[lj..lj+1]
    const int li = threadIdx.y, lj = threadIdx.x;
    float acc = t_e[li][lj] + 6.f * t_e[li][lj + 1] + t_e[li][lj + 2]
              + 4.f * (t_o[li][lj] + t_o[li][lj + 1]);
    dn[(size_t)(i0 + li) * N2 + (j0 + lj)] = acc * (1.0f / 256.0f);
}

// -------------------------------------------------------------------------------
// loss_kernel<LVL>: fused up -> diff -> |GX|+|GY| -> |m_in - m_tg| -> sum.
// Per-block index tables + separable upsample.
// Output grid (N+2)x(N+2); block (32,16) computes a 32x16 tile.
// -------------------------------------------------------------------------------
#define TY 16
#define TX 32
#define HT (TY + 2)   // 18
#define WT (TX + 2)   // 34
#define DR 13
#define DC 21
#define NT (TY * TX)  // 512

template <int LVL>
__global__ __launch_bounds__(512) void loss_kernel(const float* __restrict__ extA,
                                                   const float* __restrict__ extB) {
    constexpr int N  = (LVL == 0) ? 512 : (LVL == 1) ? 256 : 128;
    constexpr int N2 = N >> 1;

    const int p = blockIdx.z;
    const float *cur0, *cur1, *dn0, *dn1;
    if constexpr (LVL == 0) {
        cur0 = extA + (size_t)p * N * N;     cur1 = extB + (size_t)p * N * N;
        dn0 = g_d1[0] + (size_t)p * N2 * N2; dn1 = g_d1[1] + (size_t)p * N2 * N2;
    } else if constexpr (LVL == 1) {
        cur0 = g_d1[0] + (size_t)p * N * N;  cur1 = g_d1[1] + (size_t)p * N * N;
        dn0 = g_d2[0] + (size_t)p * N2 * N2; dn1 = g_d2[1] + (size_t)p * N2 * N2;
    } else {
        cur0 = g_d2[0] + (size_t)p * N * N;  cur1 = g_d2[1] + (size_t)p * N * N;
        dn0 = g_d3[0] + (size_t)p * N2 * N2; dn1 = g_d3[1] + (size_t)p * N2 * N2;
    }

    __shared__ float s_dn[2][DR][DC];
    __shared__ float s_h[2][DR][WT];
    __shared__ float s_df[2][HT][WT + 1];
    __shared__ int   ci0[WT], ci1[WT], ci2[WT];
    __shared__ float cw0[WT], cw1[WT], cw2[WT];
    __shared__ int   ri0[HT], ri1[HT], ri2[HT];
    __shared__ float rw0[HT], rw1[HT], rw2[HT];
    __shared__ int   wcol[WT], growoff[HT];
    __shared__ float warpsum[16];

    const int oy0 = blockIdx.y * TY, ox0 = blockIdx.x * TX;
    const int R0 = max(0, (oy0 - 4) >> 1);
    const int C0 = max(0, (ox0 - 4) >> 1);
    const int tid = threadIdx.y * TX + threadIdx.x;

    // ---- per-block tap tables (weights pre-scaled by 1/8 per dim) ----
    if (tid < WT) {
        int j = tid;
        int w = refl(ox0 - 2 + j, N);
        wcol[j] = w;
        int a, b, c; float x, y, zz;
        if (w & 1) { a = refl(w - 1, N) >> 1; b = refl(w + 1, N) >> 1; c = a;
                     x = 0.5f; y = 0.5f; zz = 0.f; }
        else       { a = refl(w - 2, N) >> 1; b = w >> 1; c = refl(w + 2, N) >> 1;
                     x = 0.125f; y = 0.75f; zz = 0.125f; }
        ci0[j] = min(max(a - C0, 0), DC - 1);
        ci1[j] = min(max(b - C0, 0), DC - 1);
        ci2[j] = min(max(c - C0, 0), DC - 1);
        cw0[j] = x; cw1[j] = y; cw2[j] = zz;
    } else if (tid < WT + HT) {
        int i = tid - WT;
        int h = refl(oy0 - 2 + i, N);
        growoff[i] = h * N;
        int a, b, c; float x, y, zz;
        if (h & 1) { a = refl(h - 1, N) >> 1; b = refl(h + 1, N) >> 1; c = a;
                     x = 0.5f; y = 0.5f; zz = 0.f; }
        else       { a = refl(h - 2, N) >> 1; b = h >> 1; c = refl(h + 2, N) >> 1;
                     x = 0.125f; y = 0.75f; zz = 0.125f; }
        ri0[i] = min(max(a - R0, 0), DR - 1);
        ri1[i] = min(max(b - R0, 0), DR - 1);
        ri2[i] = min(max(c - R0, 0), DR - 1);
        rw0[i] = x; rw1[i] = y; rw2[i] = zz;
    }

    // ---- load down windows (clamped edges never hit by valid taps) ----
    for (int idx = tid; idx < 2 * DR * DC; idx += NT) {
        int img = idx >= DR * DC;
        int rem = img ? idx - DR * DC : idx;
        int r = rem / DC, c = rem - r * DC;
        int rr = min(R0 + r, N2 - 1);
        int cc = min(C0 + c, N2 - 1);
        const float* dn = img ? dn1 : dn0;
        s_dn[img][r][c] = __ldg(&dn[(size_t)rr * N2 + cc]);
    }
    __syncthreads();

    // ---- horizontal up pass over down rows ----
    for (int idx = tid; idx < 2 * DR * WT; idx += NT) {
        int img = idx >= DR * WT;
        int rem = img ? idx - DR * WT : idx;
        int r = rem / WT, j = rem - r * WT;
        s_h[img][r][j] = cw0[j] * s_dn[img][r][ci0[j]]
                       + cw1[j] * s_dn[img][r][ci1[j]]
                       + cw2[j] * s_dn[img][r][ci2[j]];
    }
    __syncthreads();

    // ---- vertical up pass fused with cur load -> diff tile ----
    for (int idx = tid; idx < 2 * HT * WT; idx += NT) {
        int img = idx >= HT * WT;
        int rem = img ? idx - HT * WT : idx;
        int i = rem / WT, j = rem - i * WT;
        float up = rw0[i] * s_h[img][ri0[i]][j]
                 + rw1[i] * s_h[img][ri1[i]][j]
                 + rw2[i] * s_h[img][ri2[i]][j];
        const float* cur = img ? cur1 : cur0;
        s_df[img][i][j] = __ldg(&cur[growoff[i] + wcol[j]]) - up;
    }
    __syncthreads();

    // ---- |GX*diff| + |GY*diff| per image, then |m0 - m1| ----
    float val = 0.f;
    const int oy = oy0 + threadIdx.y, ox = ox0 + threadIdx.x;
    if (oy < N + 2 && ox < N + 2) {
        float m[2];
#pragma unroll
        for (int img = 0; img < 2; img++) {
            float d00 = s_df[img][threadIdx.y + 0][threadIdx.x + 0];
            float d01 = s_df[img][threadIdx.y + 0][threadIdx.x + 1];
            float d02 = s_df[img][threadIdx.y + 0][threadIdx.x + 2];
            float d10 = s_df[img][threadIdx.y + 1][threadIdx.x + 0];
            float d12 = s_df[img][threadIdx.y + 1][threadIdx.x + 2];
            float d20 = s_df[img][threadIdx.y + 2][threadIdx.x + 0];
            float d21 = s_df[img][threadIdx.y + 2][threadIdx.x + 1];
            float d22 = s_df[img][threadIdx.y + 2][threadIdx.x + 2];
            float gx = 2.f * (d00 - d02) + 4.f * (d10 - d12) + 2.f * (d20 - d22);
            float gy = 2.f * (d00 - d20) + 4.f * (d01 - d21) + 2.f * (d02 - d22);
            m[img] = fabsf(gx) + fabsf(gy);
        }
        val = fabsf(m[0] - m[1]);
    }

    // ---- block reduction -> one double atomic per block ----
#pragma unroll
    for (int off = 16; off > 0; off >>= 1)
        val += __shfl_down_sync(0xffffffffu, val, off);
    if ((tid & 31) == 0) warpsum[tid >> 5] = val;
    __syncthreads();
    if (tid < 16) {
        float v = warpsum[tid];
#pragma unroll
        for (int off = 8; off > 0; off >>= 1)
            v += __shfl_down_sync(0xffffu, v, off);
        if (tid == 0) atomicAdd(&g_acc[LVL], (double)v);
    }
}

__global__ void finalize_kernel(float* __restrict__ out) {
    double l = g_acc[0] / ((double)PLANES * 514.0 * 514.0)
             + g_acc[1] / ((double)PLANES * 258.0 * 258.0)
             + g_acc[2] / ((double)PLANES * 130.0 * 130.0);
    out[0] = (float)l;
}

// -------------------------------------------------------------------------------
extern "C" void kernel_launch(void* const* d_in, const int* in_sizes, int n_in,
                              void* d_out, int out_size) {
    const float* inp = (const float*)d_in[0];
    const float* tgt = (const float*)d_in[1];
    // d_in[2] (gauss_kernel) is a fixed constant — baked into the kernels.
    float* out = (float*)d_out;

    zero_acc_kernel<<<1, 32>>>();

    // level 0 (512)
    down_kernel<0><<<dim3(8, 32, 96), dim3(32, 8)>>>(inp, tgt);
    loss_kernel<0><<<dim3(17, 33, PLANES), dim3(TX, TY)>>>(inp, tgt);
    // level 1 (256)
    down_kernel<1><<<dim3(4, 16, 96), dim3(32, 8)>>>(inp, tgt);
    loss_kernel<1><<<dim3(9, 17, PLANES), dim3(TX, TY)>>>(inp, tgt);
    // level 2 (128)
    down_kernel<2><<<dim3(2, 8, 96), dim3(32, 8)>>>(inp, tgt);
    loss_kernel<2><<<dim3(5, 9, PLANES), dim3(TX, TY)>>>(inp, tgt);

    finalize_kernel<<<1, 1>>>(out);
}

// round 6
// speedup vs baseline: 1.0030x; 1.0030x over previous
#include <cuda_runtime.h>
#include <cuda_bf16.h>

#define PLANES 48  // B*C = 16*3

// ---------------- static device scratch (no allocations allowed) ----------------
__device__ float g_d1[2][PLANES * 256 * 256];  // level-0 downs == level-1 currents
__device__ float g_d2[2][PLANES * 128 * 128];  // level-1 downs == level-2 currents
__device__ float g_d3[2][PLANES * 64 * 64];    // level-2 downs
__device__ double g_acc[3];                    // per-level |.| sums

// reflect index (numpy 'reflect', pad<=2): -1->1, -2->2, n->n-2, n+1->n-3
__device__ __forceinline__ int refl(int p, int n) {
    p = (p < 0) ? -p : p;
    return (p >= n) ? (2 * n - 2 - p) : p;
}

__global__ void zero_acc_kernel() {
    if (threadIdx.x < 3) g_acc[threadIdx.x] = 0.0;
}

// -------------------------------------------------------------------------------
// down_kernel<LVL>: 5x5 reflect gauss + ::2 decimation, separable.
// block (32,8) -> 32x8 down pixels.  grid: (N2/32, N2/8, 96); z<48 -> image A.
// All loops are 2-D strided with pow-2 strides: no integer division anywhere.
// -------------------------------------------------------------------------------
template <int LVL>
__global__ __launch_bounds__(256) void down_kernel(const float* __restrict__ extA,
                                                   const float* __restrict__ extB) {
    constexpr int N  = (LVL == 0) ? 512 : (LVL == 1) ? 256 : 128;
    constexpr int N2 = N >> 1;

    const int z = blockIdx.z;
    const int p = (z < PLANES) ? z : z - PLANES;
    const float* cur;
    float* dn;
    if constexpr (LVL == 0) {
        cur = ((z < PLANES) ? extA : extB) + (size_t)p * N * N;
        dn  = ((z < PLANES) ? g_d1[0] : g_d1[1]) + (size_t)p * N2 * N2;
    } else if constexpr (LVL == 1) {
        cur = ((z < PLANES) ? g_d1[0] : g_d1[1]) + (size_t)p * N * N;
        dn  = ((z < PLANES) ? g_d2[0] : g_d2[1]) + (size_t)p * N2 * N2;
    } else {
        cur = ((z < PLANES) ? g_d2[0] : g_d2[1]) + (size_t)p * N * N;
        dn  = ((z < PLANES) ? g_d3[0] : g_d3[1]) + (size_t)p * N2 * N2;
    }

    __shared__ float s[19][68];   // source tile (reflected)
    __shared__ float t[8][68];    // vertically filtered at down rows
    __shared__ int colmap[67];
    __shared__ int rowoff[19];

    const int ty = threadIdx.y, tx = threadIdx.x;
    const int i0 = blockIdx.y * 8, j0 = blockIdx.x * 32;
    const int r0 = 2 * i0 - 2, c0 = 2 * j0 - 2;
    const int tid = ty * 32 + tx;

    if (tid < 67) colmap[tid] = refl(c0 + tid, N);
    else if (tid < 67 + 19) rowoff[tid - 67] = refl(r0 + tid - 67, N) * N;
    __syncthreads();

    // load 19x67 tile: rows stride 8, cols stride 32 (no division)
#pragma unroll
    for (int r = ty; r < 19; r += 8) {
        const int ro = rowoff[r];
#pragma unroll
        for (int c = tx; c < 67; c += 32)
            s[r][c] = __ldg(&cur[ro + colmap[c]]);
    }
    __syncthreads();

    // vertical 5-tap [1,4,6,4,1] at down row ty (exactly 8 rows)
    {
        const int r2 = 2 * ty;
#pragma unroll
        for (int c = tx; c < 67; c += 32)
            t[ty][c] = s[r2][c] + 4.f * s[r2 + 1][c] + 6.f * s[r2 + 2][c]
                     + 4.f * s[r2 + 3][c] + s[r2 + 4][c];
    }
    __syncthreads();

    // horizontal 5-tap at stride-2 positions
    const int c2 = 2 * tx;
    float acc = t[ty][c2] + 4.f * t[ty][c2 + 1] + 6.f * t[ty][c2 + 2]
              + 4.f * t[ty][c2 + 3] + t[ty][c2 + 4];
    dn[(size_t)(i0 + ty) * N2 + (j0 + tx)] = acc * (1.0f / 256.0f);
}

// -------------------------------------------------------------------------------
// loss_kernel<LVL>: fused up -> diff -> |GX|+|GY| -> |m_in - m_tg| -> sum.
// block (32,16); ty>>3 selects image, all loops pow-2 strided: no division.
// -------------------------------------------------------------------------------
#define TY 16
#define TX 32
#define HT (TY + 2)   // 18
#define WT (TX + 2)   // 34
#define DR 13
#define DC 21

template <int LVL>
__global__ __launch_bounds__(512) void loss_kernel(const float* __restrict__ extA,
                                                   const float* __restrict__ extB) {
    constexpr int N  = (LVL == 0) ? 512 : (LVL == 1) ? 256 : 128;
    constexpr int N2 = N >> 1;

    const int p = blockIdx.z;
    const float *cur0, *cur1, *dn0, *dn1;
    if constexpr (LVL == 0) {
        cur0 = extA + (size_t)p * N * N;     cur1 = extB + (size_t)p * N * N;
        dn0 = g_d1[0] + (size_t)p * N2 * N2; dn1 = g_d1[1] + (size_t)p * N2 * N2;
    } else if constexpr (LVL == 1) {
        cur0 = g_d1[0] + (size_t)p * N * N;  cur1 = g_d1[1] + (size_t)p * N * N;
        dn0 = g_d2[0] + (size_t)p * N2 * N2; dn1 = g_d2[1] + (size_t)p * N2 * N2;
    } else {
        cur0 = g_d2[0] + (size_t)p * N * N;  cur1 = g_d2[1] + (size_t)p * N * N;
        dn0 = g_d3[0] + (size_t)p * N2 * N2; dn1 = g_d3[1] + (size_t)p * N2 * N2;
    }

    __shared__ float s_dn[2][DR][DC];
    __shared__ float s_h[2][DR][WT];
    __shared__ float s_df[2][HT][WT + 1];
    __shared__ int   ci0[WT], ci1[WT], ci2[WT];
    __shared__ float cw0[WT], cw1[WT], cw2[WT];
    __shared__ int   ri0[HT], ri1[HT], ri2[HT];
    __shared__ float rw0[HT], rw1[HT], rw2[HT];
    __shared__ int   wcol[WT], growoff[HT];
    __shared__ float warpsum[16];

    const int ty = threadIdx.y, tx = threadIdx.x;
    const int img = ty >> 3;          // 0 or 1
    const int ty8 = ty & 7;           // 0..7
    const int oy0 = blockIdx.y * TY, ox0 = blockIdx.x * TX;
    const int R0 = max(0, (oy0 - 4) >> 1);
    const int C0 = max(0, (ox0 - 4) >> 1);
    const int tid = ty * TX + tx;

    // ---- per-block tap tables (weights pre-scaled by 1/8 per dim) ----
    if (tid < WT) {
        const int j = tid;
        const int w = refl(ox0 - 2 + j, N);
        wcol[j] = w;
        int a, b, c; float x, y, zz;
        if (w & 1) { a = refl(w - 1, N) >> 1; b = refl(w + 1, N) >> 1; c = a;
                     x = 0.5f; y = 0.5f; zz = 0.f; }
        else       { a = refl(w - 2, N) >> 1; b = w >> 1; c = refl(w + 2, N) >> 1;
                     x = 0.125f; y = 0.75f; zz = 0.125f; }
        ci0[j] = min(max(a - C0, 0), DC - 1);
        ci1[j] = min(max(b - C0, 0), DC - 1);
        ci2[j] = min(max(c - C0, 0), DC - 1);
        cw0[j] = x; cw1[j] = y; cw2[j] = zz;
    } else if (tid < WT + HT) {
        const int i = tid - WT;
        const int h = refl(oy0 - 2 + i, N);
        growoff[i] = h * N;
        int a, b, c; float x, y, zz;
        if (h & 1) { a = refl(h - 1, N) >> 1; b = refl(h + 1, N) >> 1; c = a;
                     x = 0.5f; y = 0.5f; zz = 0.f; }
        else       { a = refl(h - 2, N) >> 1; b = h >> 1; c = refl(h + 2, N) >> 1;
                     x = 0.125f; y = 0.75f; zz = 0.125f; }
        ri0[i] = min(max(a - R0, 0), DR - 1);
        ri1[i] = min(max(b - R0, 0), DR - 1);
        ri2[i] = min(max(c - R0, 0), DR - 1);
        rw0[i] = x; rw1[i] = y; rw2[i] = zz;
    }

    // ---- load down windows (same phase as tables; sync covers both) ----
    {
        const float* dnI = img ? dn1 : dn0;
        if (tx < DC) {
            const int cc = min(C0 + tx, N2 - 1);
#pragma unroll
            for (int r = ty8; r < DR; r += 8) {
                const int rr = min(R0 + r, N2 - 1);
                s_dn[img][r][tx] = __ldg(&dnI[(size_t)rr * N2 + cc]);
            }
        }
    }
    __syncthreads();

    // ---- horizontal up pass over down rows ----
#pragma unroll
    for (int r = ty8; r < DR; r += 8) {
#pragma unroll
        for (int j = tx; j < WT; j += 32)
            s_h[img][r][j] = cw0[j] * s_dn[img][r][ci0[j]]
                           + cw1[j] * s_dn[img][r][ci1[j]]
                           + cw2[j] * s_dn[img][r][ci2[j]];
    }
    __syncthreads();

    // ---- vertical up pass fused with cur load -> diff tile ----
    {
        const float* curI = img ? cur1 : cur0;
#pragma unroll
        for (int i = ty8; i < HT; i += 8) {
            const float w0 = rw0[i], w1 = rw1[i], w2 = rw2[i];
            const int a = ri0[i], b = ri1[i], c = ri2[i];
            const int go = growoff[i];
#pragma unroll
            for (int j = tx; j < WT; j += 32) {
                float up = w0 * s_h[img][a][j] + w1 * s_h[img][b][j]
                         + w2 * s_h[img][c][j];
                s_df[img][i][j] = __ldg(&curI[go + wcol[j]]) - up;
            }
        }
    }
    __syncthreads();

    // ---- |GX*diff| + |GY*diff| per image, then |m0 - m1| ----
    float val = 0.f;
    const int oy = oy0 + ty, ox = ox0 + tx;
    if (oy < N + 2 && ox < N + 2) {
        float m[2];
#pragma unroll
        for (int im = 0; im < 2; im++) {
            float d00 = s_df[im][ty + 0][tx + 0];
            float d01 = s_df[im][ty + 0][tx + 1];
            float d02 = s_df[im][ty + 0][tx + 2];
            float d10 = s_df[im][ty + 1][tx + 0];
            float d12 = s_df[im][ty + 1][tx + 2];
            float d20 = s_df[im][ty + 2][tx + 0];
            float d21 = s_df[im][ty + 2][tx + 1];
            float d22 = s_df[im][ty + 2][tx + 2];
            float gx = 2.f * (d00 - d02) + 4.f * (d10 - d12) + 2.f * (d20 - d22);
            float gy = 2.f * (d00 - d20) + 4.f * (d01 - d21) + 2.f * (d02 - d22);
            m[im] = fabsf(gx) + fabsf(gy);
        }
        val = fabsf(m[0] - m[1]);
    }

    // ---- block reduction -> one double atomic per block ----
#pragma unroll
    for (int off = 16; off > 0; off >>= 1)
        val += __shfl_down_sync(0xffffffffu, val, off);
    if ((tid & 31) == 0) warpsum[tid >> 5] = val;
    __syncthreads();
    if (tid < 16) {
        float v = warpsum[tid];
#pragma unroll
        for (int off = 8; off > 0; off >>= 1)
            v += __shfl_down_sync(0xffffu, v, off);
        if (tid == 0) atomicAdd(&g_acc[LVL], (double)v);
    }
}

__global__ void finalize_kernel(float* __restrict__ out) {
    double l = g_acc[0] / ((double)PLANES * 514.0 * 514.0)
             + g_acc[1] / ((double)PLANES * 258.0 * 258.0)
             + g_acc[2] / ((double)PLANES * 130.0 * 130.0);
    out[0] = (float)l;
}

// -------------------------------------------------------------------------------
extern "C" void kernel_launch(void* const* d_in, const int* in_sizes, int n_in,
                              void* d_out, int out_size) {
    const float* inp = (const float*)d_in[0];
    const float* tgt = (const float*)d_in[1];
    // d_in[2] (gauss_kernel) is a fixed constant — baked into the kernels.
    float* out = (float*)d_out;

    zero_acc_kernel<<<1, 32>>>();

    // level 0 (512)
    down_kernel<0><<<dim3(8, 32, 96), dim3(32, 8)>>>(inp, tgt);
    loss_kernel<0><<<dim3(17, 33, PLANES), dim3(TX, TY)>>>(inp, tgt);
    // level 1 (256)
    down_kernel<1><<<dim3(4, 16, 96), dim3(32, 8)>>>(inp, tgt);
    loss_kernel<1><<<dim3(9, 17, PLANES), dim3(TX, TY)>>>(inp, tgt);
    // level 2 (128)
    down_kernel<2><<<dim3(2, 8, 96), dim3(32, 8)>>>(inp, tgt);
    loss_kernel<2><<<dim3(5, 9, PLANES), dim3(TX, TY)>>>(inp, tgt);

    finalize_kernel<<<1, 1>>>(out);
}

// round 7
// speedup vs baseline: 1.1089x; 1.1056x over previous
#include <cuda_runtime.h>

#define PLANES 48  // B*C = 16*3

// ---------------- static device scratch (no allocations allowed) ----------------
__device__ float g_d1[2][PLANES * 256 * 256];  // level-0 downs == level-1 currents
__device__ float g_d2[2][PLANES * 128 * 128];  // level-1 downs == level-2 currents
__device__ double g_acc[3];                    // per-level |.| sums

// reflect index (numpy 'reflect', pad<=2): -1->1, -2->2, n->n-2, n+1->n-3
__device__ __forceinline__ int refl(int p, int n) {
    p = (p < 0) ? -p : p;
    return (p >= n) ? (2 * n - 2 - p) : p;
}

__global__ void zero_acc_kernel() {
    if (threadIdx.x < 3) g_acc[threadIdx.x] = 0.0;
}

// -------------------------------------------------------------------------------
// lap_kernel<LVL>: ONE kernel per pyramid level.
//   per block: loss output tile 32 rows x 64 cols of the (N+2)x(N+2) grid.
//   - load cur tile 43x77 (reflected) into smem ONCE
//   - compute down window 20x37 in smem (5x5 gauss, stride 2); write the
//     block-owned 16x32 piece to the next level's input
//   - separable upsample (h-pass then v-pass fused with diff, cur from smem)
//   - |GX|+|GY| sobel per image, |m_in - m_tg|, block reduce, one atomic
// block (32,16)=512 threads; grid (ceil((N+2)/64), ceil((N+2)/32), 48)
// -------------------------------------------------------------------------------
template <int LVL>
__global__ __launch_bounds__(512) void lap_kernel(const float* __restrict__ extA,
                                                  const float* __restrict__ extB) {
    constexpr int N  = (LVL == 0) ? 512 : (LVL == 1) ? 256 : 128;
    constexpr int N2 = N >> 1;

    const int p = blockIdx.z;
    const float *cur0, *cur1;
    float *dn0 = nullptr, *dn1 = nullptr;
    if constexpr (LVL == 0) {
        cur0 = extA + (size_t)p * N * N;     cur1 = extB + (size_t)p * N * N;
        dn0 = g_d1[0] + (size_t)p * N2 * N2; dn1 = g_d1[1] + (size_t)p * N2 * N2;
    } else if constexpr (LVL == 1) {
        cur0 = g_d1[0] + (size_t)p * N * N;  cur1 = g_d1[1] + (size_t)p * N * N;
        dn0 = g_d2[0] + (size_t)p * N2 * N2; dn1 = g_d2[1] + (size_t)p * N2 * N2;
    } else {
        cur0 = g_d2[0] + (size_t)p * N * N;  cur1 = g_d2[1] + (size_t)p * N * N;
    }

    __shared__ float s_cur[43][78];     // reflected cur tile (reused per image)
    __shared__ float s_dw[20][38];      // down window (reused per image)
    __shared__ float s_h[20][67];       // horizontally upsampled down rows
    __shared__ float s_df[2][34][67];   // diff tiles, both images
    __shared__ int rowoffT[43], colmapT[77];
    __shared__ int shi[34], riT[34][3];
    __shared__ float rwT[34][3];
    __shared__ int swj[66], ciT[66][3];
    __shared__ float cwT[66][3];
    __shared__ float warpsum[16];

    const int tx = threadIdx.x, ty = threadIdx.y;
    const int tid = ty * 32 + tx;
    const int oy0 = blockIdx.y * 32, ox0 = blockIdx.x * 64;
    const int R0 = max(0, (oy0 - 4) >> 1);
    const int C0 = max(0, (ox0 - 4) >> 1);
    const int gr0 = 2 * R0 - 2;   // cur tile global row 0
    const int gc0 = 2 * C0 - 2;   // cur tile global col 0

    // ---- per-block tables (one time) ----
    if (tid < 43) {
        rowoffT[tid] = refl(gr0 + tid, N) * N;
    } else if (tid < 120) {
        colmapT[tid - 43] = refl(gc0 + tid - 43, N);
    } else if (tid < 154) {
        const int i = tid - 120;
        const int h = refl(oy0 - 2 + i, N);
        shi[i] = min(max(h - gr0, 0), 42);
        int a, b, c; float x, y, z;
        if (h & 1) { a = refl(h - 1, N) >> 1; b = refl(h + 1, N) >> 1; c = a;
                     x = 0.5f; y = 0.5f; z = 0.f; }
        else       { a = refl(h - 2, N) >> 1; b = h >> 1; c = refl(h + 2, N) >> 1;
                     x = 0.125f; y = 0.75f; z = 0.125f; }
        riT[i][0] = min(max(a - R0, 0), 19);
        riT[i][1] = min(max(b - R0, 0), 19);
        riT[i][2] = min(max(c - R0, 0), 19);
        rwT[i][0] = x; rwT[i][1] = y; rwT[i][2] = z;
    } else if (tid < 220) {
        const int j = tid - 154;
        const int w = refl(ox0 - 2 + j, N);
        swj[j] = min(max(w - gc0, 0), 76);
        int a, b, c; float x, y, z;
        if (w & 1) { a = refl(w - 1, N) >> 1; b = refl(w + 1, N) >> 1; c = a;
                     x = 0.5f; y = 0.5f; z = 0.f; }
        else       { a = refl(w - 2, N) >> 1; b = w >> 1; c = refl(w + 2, N) >> 1;
                     x = 0.125f; y = 0.75f; z = 0.125f; }
        ciT[j][0] = min(max(a - C0, 0), 36);
        ciT[j][1] = min(max(b - C0, 0), 36);
        ciT[j][2] = min(max(c - C0, 0), 36);
        cwT[j][0] = x; cwT[j][1] = y; cwT[j][2] = z;
    }
    __syncthreads();

    for (int img = 0; img < 2; img++) {
        const float* cur = img ? cur1 : cur0;

        // ---- A: load cur tile 43x77 (coalesced rows, deep MLP) ----
#pragma unroll
        for (int r = ty; r < 43; r += 16) {
            const int ro = rowoffT[r];
#pragma unroll
            for (int c = tx; c < 77; c += 32)
                s_cur[r][c] = __ldg(&cur[ro + colmapT[c]]);
        }
        __syncthreads();

        // ---- B: down window 20x37 (5x5 gauss at stride-2 positions) ----
#pragma unroll
        for (int r = ty; r < 20; r += 16) {
            const int rs = 2 * (min(R0 + r, N2 - 1) - R0);
#pragma unroll
            for (int c = tx; c < 37; c += 32) {
                const int cs = 2 * (min(C0 + c, N2 - 1) - C0);
                float acc = 0.f;
#pragma unroll
                for (int ky = 0; ky < 5; ky++) {
                    const float gy = (ky == 0 || ky == 4) ? 1.f : ((ky == 2) ? 6.f : 4.f);
                    float rsum = s_cur[rs + ky][cs]
                               + 4.f * s_cur[rs + ky][cs + 1]
                               + 6.f * s_cur[rs + ky][cs + 2]
                               + 4.f * s_cur[rs + ky][cs + 3]
                               +       s_cur[rs + ky][cs + 4];
                    acc += gy * rsum;
                }
                s_dw[r][c] = acc * (1.0f / 256.0f);
            }
        }
        __syncthreads();

        // ---- B2: write block-owned 16x32 down piece for the next level ----
        if constexpr (LVL < 2) {
            const int bi = blockIdx.y, bj = blockIdx.x;
            if (bi < (N2 >> 4) && bj < (N2 >> 5)) {
                float* dn = img ? dn1 : dn0;
                dn[(size_t)((bi << 4) + ty) * N2 + (bj << 5) + tx] =
                    s_dw[(bi << 4) - R0 + ty][(bj << 5) - C0 + tx];
            }
        }

        // ---- C: horizontal up pass over down rows ----
#pragma unroll
        for (int r = ty; r < 20; r += 16) {
#pragma unroll
            for (int j = tx; j < 66; j += 32)
                s_h[r][j] = cwT[j][0] * s_dw[r][ciT[j][0]]
                          + cwT[j][1] * s_dw[r][ciT[j][1]]
                          + cwT[j][2] * s_dw[r][ciT[j][2]];
        }
        __syncthreads();

        // ---- D: vertical up pass + diff (cur from smem tile) ----
#pragma unroll
        for (int i = ty; i < 34; i += 16) {
            const float w0 = rwT[i][0], w1 = rwT[i][1], w2 = rwT[i][2];
            const int a = riT[i][0], b = riT[i][1], cix = riT[i][2];
            const int hs = shi[i];
#pragma unroll
            for (int j = tx; j < 66; j += 32)
                s_df[img][i][j] = s_cur[hs][swj[j]]
                    - (w0 * s_h[a][j] + w1 * s_h[b][j] + w2 * s_h[cix][j]);
        }
        __syncthreads();
    }

    // ---- E: sobel |GX|+|GY| per image, |m0-m1|, 4 outputs per thread ----
    float val = 0.f;
#pragma unroll
    for (int q = 0; q < 4; q++) {
        const int r = ty + ((q & 2) << 3);   // ty or ty+16
        const int c = tx + ((q & 1) << 5);   // tx or tx+32
        if (oy0 + r < N + 2 && ox0 + c < N + 2) {
            float m[2];
#pragma unroll
            for (int im = 0; im < 2; im++) {
                float d00 = s_df[im][r + 0][c + 0];
                float d01 = s_df[im][r + 0][c + 1];
                float d02 = s_df[im][r + 0][c + 2];
                float d10 = s_df[im][r + 1][c + 0];
                float d12 = s_df[im][r + 1][c + 2];
                float d20 = s_df[im][r + 2][c + 0];
                float d21 = s_df[im][r + 2][c + 1];
                float d22 = s_df[im][r + 2][c + 2];
                float gx = 2.f * (d00 - d02) + 4.f * (d10 - d12) + 2.f * (d20 - d22);
                float gy = 2.f * (d00 - d20) + 4.f * (d01 - d21) + 2.f * (d02 - d22);
                m[im] = fabsf(gx) + fabsf(gy);
            }
            val += fabsf(m[0] - m[1]);
        }
    }

    // ---- block reduction -> one double atomic per block ----
#pragma unroll
    for (int off = 16; off > 0; off >>= 1)
        val += __shfl_down_sync(0xffffffffu, val, off);
    if ((tid & 31) == 0) warpsum[tid >> 5] = val;
    __syncthreads();
    if (tid < 16) {
        float v = warpsum[tid];
#pragma unroll
        for (int off = 8; off > 0; off >>= 1)
            v += __shfl_down_sync(0xffffu, v, off);
        if (tid == 0) atomicAdd(&g_acc[LVL], (double)v);
    }
}

__global__ void finalize_kernel(float* __restrict__ out) {
    double l = g_acc[0] / ((double)PLANES * 514.0 * 514.0)
             + g_acc[1] / ((double)PLANES * 258.0 * 258.0)
             + g_acc[2] / ((double)PLANES * 130.0 * 130.0);
    out[0] = (float)l;
}

// -------------------------------------------------------------------------------
extern "C" void kernel_launch(void* const* d_in, const int* in_sizes, int n_in,
                              void* d_out, int out_size) {
    const float* inp = (const float*)d_in[0];
    const float* tgt = (const float*)d_in[1];
    // d_in[2] (gauss_kernel) is a fixed constant — baked into the kernels.
    float* out = (float*)d_out;

    zero_acc_kernel<<<1, 32>>>();

    lap_kernel<0><<<dim3(9, 17, PLANES), dim3(32, 16)>>>(inp, tgt);  // N=512
    lap_kernel<1><<<dim3(5, 9, PLANES),  dim3(32, 16)>>>(inp, tgt);  // N=256
    lap_kernel<2><<<dim3(3, 5, PLANES),  dim3(32, 16)>>>(inp, tgt);  // N=128

    finalize_kernel<<<1, 1>>>(out);
}

// round 8
// speedup vs baseline: 1.2213x; 1.1013x over previous
#include <cuda_runtime.h>

#define PLANES 48  // B*C = 16*3

// ---------------- static device scratch (no allocations allowed) ----------------
__device__ float g_d1[2][PLANES * 256 * 256];  // level-0 downs == level-1 currents
__device__ float g_d2[2][PLANES * 128 * 128];  // level-1 downs == level-2 currents
__device__ double g_acc[3];                    // per-level |.| sums

// reflect index (numpy 'reflect', pad<=2): -1->1, -2->2, n->n-2, n+1->n-3
__device__ __forceinline__ int refl(int p, int n) {
    p = (p < 0) ? -p : p;
    return (p >= n) ? (2 * n - 2 - p) : p;
}

__global__ void zero_acc_kernel() {
    if (threadIdx.x < 3) g_acc[threadIdx.x] = 0.0;
}

// -------------------------------------------------------------------------------
// lap_kernel<LVL>: ONE kernel per pyramid level (fused down+up+diff+sobel+reduce).
//   per block: loss output tile 32 rows x 64 cols of the (N+2)x(N+2) grid.
// block (32,16)=512 threads; grid (ceil((N+2)/64), ceil((N+2)/32), 48)
// -------------------------------------------------------------------------------
template <int LVL>
__global__ __launch_bounds__(512) void lap_kernel(const float* __restrict__ extA,
                                                  const float* __restrict__ extB) {
    constexpr int N  = (LVL == 0) ? 512 : (LVL == 1) ? 256 : 128;
    constexpr int N2 = N >> 1;

    const int p = blockIdx.z;
    const float *cur0, *cur1;
    float *dn0 = nullptr, *dn1 = nullptr;
    if constexpr (LVL == 0) {
        cur0 = extA + (size_t)p * N * N;     cur1 = extB + (size_t)p * N * N;
        dn0 = g_d1[0] + (size_t)p * N2 * N2; dn1 = g_d1[1] + (size_t)p * N2 * N2;
    } else if constexpr (LVL == 1) {
        cur0 = g_d1[0] + (size_t)p * N * N;  cur1 = g_d1[1] + (size_t)p * N * N;
        dn0 = g_d2[0] + (size_t)p * N2 * N2; dn1 = g_d2[1] + (size_t)p * N2 * N2;
    } else {
        cur0 = g_d2[0] + (size_t)p * N * N;  cur1 = g_d2[1] + (size_t)p * N * N;
    }

    __shared__ float s_cur[43][78];                  // reflected cur tile (per image)
    __shared__ float s_dw[20][38];                   // down window (per image)
    __shared__ float s_h[20][68];                    // horizontally upsampled rows
    __shared__ __align__(16) float s_df[2][34][68];  // diff tiles (also phase-B scratch)
    __shared__ int rowoffT[43], colmapT[77];
    __shared__ int shi[34], riT[34][3];
    __shared__ float rwT[34][3];
    __shared__ int swj[66], ciT[66][3];
    __shared__ float cwT[66][3];
    __shared__ float warpsum[16];

    const int tx = threadIdx.x, ty = threadIdx.y;
    const int tid = ty * 32 + tx;
    const int oy0 = blockIdx.y * 32, ox0 = blockIdx.x * 64;
    const int R0 = max(0, (oy0 - 4) >> 1);
    const int C0 = max(0, (ox0 - 4) >> 1);
    const int gr0 = 2 * R0 - 2;   // cur tile global row 0
    const int gc0 = 2 * C0 - 2;   // cur tile global col 0

    // ---- per-block tables (one time) ----
    if (tid < 43) {
        rowoffT[tid] = refl(gr0 + tid, N) * N;
    } else if (tid < 120) {
        colmapT[tid - 43] = refl(gc0 + tid - 43, N);
    } else if (tid < 154) {
        const int i = tid - 120;
        const int h = refl(oy0 - 2 + i, N);
        shi[i] = min(max(h - gr0, 0), 42);
        int a, b, c; float x, y, z;
        if (h & 1) { a = refl(h - 1, N) >> 1; b = refl(h + 1, N) >> 1; c = a;
                     x = 0.5f; y = 0.5f; z = 0.f; }
        else       { a = refl(h - 2, N) >> 1; b = h >> 1; c = refl(h + 2, N) >> 1;
                     x = 0.125f; y = 0.75f; z = 0.125f; }
        riT[i][0] = min(max(a - R0, 0), 19);
        riT[i][1] = min(max(b - R0, 0), 19);
        riT[i][2] = min(max(c - R0, 0), 19);
        rwT[i][0] = x; rwT[i][1] = y; rwT[i][2] = z;
    } else if (tid < 220) {
        const int j = tid - 154;
        const int w = refl(ox0 - 2 + j, N);
        swj[j] = min(max(w - gc0, 0), 76);
        int a, b, c; float x, y, z;
        if (w & 1) { a = refl(w - 1, N) >> 1; b = refl(w + 1, N) >> 1; c = a;
                     x = 0.5f; y = 0.5f; z = 0.f; }
        else       { a = refl(w - 2, N) >> 1; b = w >> 1; c = refl(w + 2, N) >> 1;
                     x = 0.125f; y = 0.75f; z = 0.125f; }
        ciT[j][0] = min(max(a - C0, 0), 36);
        ciT[j][1] = min(max(b - C0, 0), 36);
        ciT[j][2] = min(max(c - C0, 0), 36);
        cwT[j][0] = x; cwT[j][1] = y; cwT[j][2] = z;
    }
    __syncthreads();

    for (int img = 0; img < 2; img++) {
        const float* cur = img ? cur1 : cur0;
        float* s_t = &s_df[img][0][0];   // phase-B scratch, dead until phase D

        // ---- A: load cur tile 43x77 (coalesced rows, deep MLP) ----
#pragma unroll
        for (int r = ty; r < 43; r += 16) {
            const int ro = rowoffT[r];
#pragma unroll
            for (int c = tx; c < 77; c += 32)
                s_cur[r][c] = __ldg(&cur[ro + colmapT[c]]);
        }
        __syncthreads();

        // ---- B1: vertical 5-tap [1,4,6,4,1] at 20 down rows over 77 cols ----
#pragma unroll
        for (int r = ty; r < 20; r += 16) {
            const int rs = 2 * (min(R0 + r, N2 - 1) - R0);
#pragma unroll
            for (int c = tx; c < 77; c += 32)
                s_t[r * 78 + c] = s_cur[rs][c] + 4.f * s_cur[rs + 1][c]
                                + 6.f * s_cur[rs + 2][c]
                                + 4.f * s_cur[rs + 3][c] + s_cur[rs + 4][c];
        }
        __syncthreads();

        // ---- B2: horizontal 5-tap at stride-2 positions -> down window 20x37 ----
#pragma unroll
        for (int r = ty; r < 20; r += 16) {
#pragma unroll
            for (int c = tx; c < 37; c += 32) {
                const int cs = 2 * (min(C0 + c, N2 - 1) - C0);
                s_dw[r][c] = (s_t[r * 78 + cs] + 4.f * s_t[r * 78 + cs + 1]
                            + 6.f * s_t[r * 78 + cs + 2]
                            + 4.f * s_t[r * 78 + cs + 3] + s_t[r * 78 + cs + 4])
                           * (1.0f / 256.0f);
            }
        }
        __syncthreads();

        // ---- B3: write block-owned 16x32 down piece for the next level ----
        if constexpr (LVL < 2) {
            const int bi = blockIdx.y, bj = blockIdx.x;
            if (bi < (N2 >> 4) && bj < (N2 >> 5)) {
                float* dn = img ? dn1 : dn0;
                dn[(size_t)((bi << 4) + ty) * N2 + (bj << 5) + tx] =
                    s_dw[(bi << 4) - R0 + ty][(bj << 5) - C0 + tx];
            }
        }

        // ---- C: horizontal up pass over down rows ----
#pragma unroll
        for (int r = ty; r < 20; r += 16) {
#pragma unroll
            for (int j = tx; j < 66; j += 32)
                s_h[r][j] = cwT[j][0] * s_dw[r][ciT[j][0]]
                          + cwT[j][1] * s_dw[r][ciT[j][1]]
                          + cwT[j][2] * s_dw[r][ciT[j][2]];
        }
        __syncthreads();

        // ---- D: vertical up pass + diff (cur from smem tile) ----
#pragma unroll
        for (int i = ty; i < 34; i += 16) {
            const float w0 = rwT[i][0], w1 = rwT[i][1], w2 = rwT[i][2];
            const int a = riT[i][0], b = riT[i][1], cix = riT[i][2];
            const int hs = shi[i];
#pragma unroll
            for (int j = tx; j < 66; j += 32)
                s_df[img][i][j] = s_cur[hs][swj[j]]
                    - (w0 * s_h[a][j] + w1 * s_h[b][j] + w2 * s_h[cix][j]);
        }
        __syncthreads();
    }

    // ---- E: sobel |GX|+|GY| per image, |m0-m1|; each thread owns a 1x4 strip ----
    // separable sobel: v[j]=2d0+4d1+2d2 -> gx(k)=v[k]-v[k+2]
    //                  u[j]=2(d0-d2)    -> gy(k)=u[k]+2u[k+1]+u[k+2]
    float val = 0.f;
    {
        const int row = tid >> 4;        // 0..31
        const int c0  = (tid & 15) << 2; // 0,4,..,60
        const bool rowok = (oy0 + row) < N + 2;
        float m0[4];
#pragma unroll
        for (int im = 0; im < 2; im++) {
            float d0[6], d1[6], d2[6];
#pragma unroll
            for (int rr = 0; rr < 3; rr++) {
                float* dst = (rr == 0) ? d0 : (rr == 1) ? d1 : d2;
                const float4 a = *(const float4*)&s_df[im][row + rr][c0];
                const float2 b = *(const float2*)&s_df[im][row + rr][c0 + 4];
                dst[0] = a.x; dst[1] = a.y; dst[2] = a.z; dst[3] = a.w;
                dst[4] = b.x; dst[5] = b.y;
            }
            float v[6], u[6];
#pragma unroll
            for (int j = 0; j < 6; j++) {
                v[j] = 2.f * d0[j] + 4.f * d1[j] + 2.f * d2[j];
                u[j] = 2.f * (d0[j] - d2[j]);
            }
#pragma unroll
            for (int k = 0; k < 4; k++) {
                float gx = v[k] - v[k + 2];
                float gy = u[k] + 2.f * u[k + 1] + u[k + 2];
                float m = fabsf(gx) + fabsf(gy);
                if (im == 0) m0[k] = m;
                else if (rowok && (ox0 + c0 + k) < N + 2)
                    val += fabsf(m0[k] - m);
            }
        }
    }

    // ---- block reduction -> one double atomic per block ----
#pragma unroll
    for (int off = 16; off > 0; off >>= 1)
        val += __shfl_down_sync(0xffffffffu, val, off);
    if ((tid & 31) == 0) warpsum[tid >> 5] = val;
    __syncthreads();
    if (tid < 16) {
        float v = warpsum[tid];
#pragma unroll
        for (int off = 8; off > 0; off >>= 1)
            v += __shfl_down_sync(0xffffu, v, off);
        if (tid == 0) atomicAdd(&g_acc[LVL], (double)v);
    }
}

__global__ void finalize_kernel(float* __restrict__ out) {
    double l = g_acc[0] / ((double)PLANES * 514.0 * 514.0)
             + g_acc[1] / ((double)PLANES * 258.0 * 258.0)
             + g_acc[2] / ((double)PLANES * 130.0 * 130.0);
    out[0] = (float)l;
}

// -------------------------------------------------------------------------------
extern "C" void kernel_launch(void* const* d_in, const int* in_sizes, int n_in,
                              void* d_out, int out_size) {
    const float* inp = (const float*)d_in[0];
    const float* tgt = (const float*)d_in[1];
    // d_in[2] (gauss_kernel) is a fixed constant — baked into the kernels.
    float* out = (float*)d_out;

    zero_acc_kernel<<<1, 32>>>();

    lap_kernel<0><<<dim3(9, 17, PLANES), dim3(32, 16)>>>(inp, tgt);  // N=512
    lap_kernel<1><<<dim3(5, 9, PLANES),  dim3(32, 16)>>>(inp, tgt);  // N=256
    lap_kernel<2><<<dim3(3, 5, PLANES),  dim3(32, 16)>>>(inp, tgt);  // N=128

    finalize_kernel<<<1, 1>>>(out);
}